// round 8
// baseline (speedup 1.0000x reference)
#include <cuda_runtime.h>
#include <cstdint>
#include <cstddef>

#define SEQ  4096
#define HID  1024
#define G4   4096
#define NCTA 128
#define SCAN_THREADS 256

typedef unsigned long long ull;

// ---------------- persistent device scratch (static: allocation-free) ----------
__device__ float g_xg[(size_t)SEQ * G4];   // 64 MB: precomputed input-side gates
// Tagged h records: (h value, tag) packed in 8B -> single-copy atomic.
// Record for h^{(s)} (state consumed at step s) lives in slot s&1 with tag s+1.
__device__ __align__(16) uint2 g_hrec[2][HID];   // 16 KB

// ---------------- packed f32x2 helpers ----------------------------------------
__device__ __forceinline__ ull pk2(float x, float y) {
  ull r; asm("mov.b64 %0, {%1, %2};" : "=l"(r) : "f"(x), "f"(y)); return r;
}
__device__ __forceinline__ void upk2(ull v, float& x, float& y) {
  asm("mov.b64 {%0, %1}, %2;" : "=f"(x), "=f"(y) : "l"(v));
}
__device__ __forceinline__ void fma2(ull& d, ull a, ull b) {
  asm("fma.rn.f32x2 %0, %1, %2, %0;" : "+l"(d) : "l"(a), "l"(b));
}

__device__ __forceinline__ float sigm(float x) {
  return __fdividef(1.0f, 1.0f + __expf(-x));
}
__device__ __forceinline__ float tanh_(float x) {
  float e = __expf(2.0f * x);
  return 1.0f - __fdividef(2.0f, e + 1.0f);
}

// strong (L2-coherent) 16B load: returns 2 records (h,tag,h,tag)
__device__ __forceinline__ uint4 ld_rec2(const uint2* p) {
  uint4 v;
  asm volatile("ld.relaxed.gpu.global.v4.b32 {%0,%1,%2,%3}, [%4];"
               : "=r"(v.x), "=r"(v.y), "=r"(v.z), "=r"(v.w) : "l"(p) : "memory");
  return v;
}
// strong 8B store: one record (h, tag) — tag travels with the payload
__device__ __forceinline__ void st_rec(uint2* p, float h, unsigned tag) {
  asm volatile("st.relaxed.gpu.global.v2.b32 [%0], {%1,%2};"
               :: "l"(p), "r"(__float_as_uint(h)), "r"(tag) : "memory");
}
// shared-memory record pair load/store (tags travel with payload in smem too)
__device__ __forceinline__ uint4 lds_rec2(uint32_t addr) {
  uint4 v;
  asm volatile("ld.shared.v4.b32 {%0,%1,%2,%3}, [%4];"
               : "=r"(v.x), "=r"(v.y), "=r"(v.z), "=r"(v.w) : "r"(addr) : "memory");
  return v;
}
__device__ __forceinline__ void sts_rec2(uint32_t addr, uint4 v) {
  asm volatile("st.shared.v4.b32 [%0], {%1,%2,%3,%4};"
               :: "r"(addr), "r"(v.x), "r"(v.y), "r"(v.z), "r"(v.w) : "memory");
}

// ==============================================================================
// Kernel 1: xg[m][n] = sum_k emb[inputs[m]][k] * W_ih[n][k] + b_ih[n] + b_hh[n]
// 128x128 tile, BK=8, 256 threads, 8x8 micro-tile via fma.rn.f32x2, 1-deep
// register prefetch pipeline. Block (0,0) also seeds the scan's h records:
// slot 0 = (h0, tag 1), slot 1 = zeros (stream-ordered before the scan).
// ==============================================================================
__global__ __launch_bounds__(256, 2) void xg_gemm(
    const int*   __restrict__ inputs,
    const float* __restrict__ emb,
    const float* __restrict__ Wih,
    const float* __restrict__ b_ih,
    const float* __restrict__ b_hh,
    const float* __restrict__ h0)
{
  if (blockIdx.x == 0 && blockIdx.y == 0) {
    for (int i = threadIdx.x; i < HID; i += 256) {
      g_hrec[0][i] = make_uint2(__float_as_uint(h0[i]), 1u);  // h^{(0)}, tag 1
      g_hrec[1][i] = make_uint2(0u, 0u);
    }
  }

  __shared__ __align__(16) float As[8][128];
  __shared__ __align__(16) float Bs[8][128];
  __shared__ int idx[128];

  const int tid = threadIdx.x;
  const int m0 = blockIdx.y << 7;
  const int n0 = blockIdx.x << 7;

  if (tid < 128) idx[tid] = inputs[m0 + tid];
  __syncthreads();

  const int lr = tid >> 1;           // 0..127 row for cooperative loads
  const int lk = (tid & 1) << 2;     // k offset 0 or 4
  const int tx = tid & 15;           // micro-tile col group
  const int ty = tid >> 4;           // micro-tile row group

  const float* aptr = emb + (size_t)idx[lr] * 1024 + lk;
  const float* bptr = Wih + (size_t)(n0 + lr) * 1024 + lk;

  ull acc2[8][4];
  #pragma unroll
  for (int i = 0; i < 8; ++i)
    #pragma unroll
    for (int p = 0; p < 4; ++p) acc2[i][p] = 0ULL;

  float4 av = *(const float4*)(aptr);
  float4 bv = *(const float4*)(bptr);

  for (int k0 = 0; k0 < 1024; k0 += 8) {
    __syncthreads();
    As[lk + 0][lr] = av.x; As[lk + 1][lr] = av.y;
    As[lk + 2][lr] = av.z; As[lk + 3][lr] = av.w;
    Bs[lk + 0][lr] = bv.x; Bs[lk + 1][lr] = bv.y;
    Bs[lk + 2][lr] = bv.z; Bs[lk + 3][lr] = bv.w;
    __syncthreads();

    const int kn = (k0 + 8 < 1024) ? (k0 + 8) : 0;
    av = *(const float4*)(aptr + kn);
    bv = *(const float4*)(bptr + kn);

    #pragma unroll
    for (int kk = 0; kk < 8; ++kk) {
      float4 a0 = *(const float4*)&As[kk][ty << 3];
      float4 a1 = *(const float4*)&As[kk][(ty << 3) + 4];
      float4 b0 = *(const float4*)&Bs[kk][tx << 3];
      float4 b1 = *(const float4*)&Bs[kk][(tx << 3) + 4];
      ull bq[4];
      bq[0] = pk2(b0.x, b0.y); bq[1] = pk2(b0.z, b0.w);
      bq[2] = pk2(b1.x, b1.y); bq[3] = pk2(b1.z, b1.w);
      float a[8] = {a0.x, a0.y, a0.z, a0.w, a1.x, a1.y, a1.z, a1.w};
      #pragma unroll
      for (int i = 0; i < 8; ++i) {
        ull ad = pk2(a[i], a[i]);
        #pragma unroll
        for (int p = 0; p < 4; ++p) fma2(acc2[i][p], ad, bq[p]);
      }
    }
  }

  float bias[8];
  #pragma unroll
  for (int p = 0; p < 8; ++p) {
    int n = n0 + (tx << 3) + p;
    bias[p] = b_ih[n] + b_hh[n];
  }
  #pragma unroll
  for (int i = 0; i < 8; ++i) {
    float c[8];
    #pragma unroll
    for (int p = 0; p < 4; ++p) upk2(acc2[i][p], c[2 * p], c[2 * p + 1]);
    #pragma unroll
    for (int p = 0; p < 8; ++p) c[p] += bias[p];
    int m = m0 + (ty << 3) + i;
    float* outp = g_xg + (size_t)m * G4 + n0 + (tx << 3);
    *(float4*)(outp)     = make_float4(c[0], c[1], c[2], c[3]);
    *(float4*)(outp + 4) = make_float4(c[4], c[5], c[6], c[7]);
  }
}

// ==============================================================================
// Kernel 2: persistent LSTM scan — fully barrier-free step loop.
// 128 CTAs x 256 threads. CTA b owns h columns [8b, 8b+8), warp w -> column j.
// Records (h, tag) are the only synchronization: fillers copy their 4 global
// records into parity-doubled SMEM once tags pass; compute warps spin on SMEM
// tags per 64-column chunk (29-cyc period) and FMA chunks as they arrive, so
// the 256-cyc FMA block overlaps producer skew. Each warp publishes its h the
// moment its gates finish. Intra-CTA skew is provably <= 1 step, so the
// 2-parity slots never collide; tag versioning kills all stale reads.
// ==============================================================================
__global__ __launch_bounds__(SCAN_THREADS, 1) void lstm_scan(
    const float* __restrict__ W_hh,
    const float* __restrict__ c0)
{
  const int tid  = threadIdx.x;
  const int lane = tid & 31;
  const int w    = tid >> 5;                  // warp 0..7
  const int j    = (blockIdx.x << 3) + w;     // 0..1023

  __shared__ __align__(16) uint2 sh_rec[2][HID];   // 16 KB, parity-doubled
  const uint32_t sbase = (uint32_t)__cvta_generic_to_shared(&sh_rec[0][0]);

  // zero all smem tags (uninitialized smem could fake a ready tag)
  {
    uint4 z = make_uint4(0u, 0u, 0u, 0u);
    for (int i = tid; i < HID; i += SCAN_THREADS)   // HID 16B-chunks = 2*HID records
      sts_rec2(sbase + i * 16, z);
  }

  // load this thread's 128 weights (as 64 f32x2 pairs) into registers
  ull wreg[4][16];
  #pragma unroll
  for (int g = 0; g < 4; ++g) {
    const float* wp = W_hh + (size_t)(j + (g << 10)) * HID;
    #pragma unroll
    for (int i = 0; i < 16; ++i) {
      float2 v = *(const float2*)(wp + 2 * (lane + 32 * i));
      wreg[g][i] = pk2(v.x, v.y);
    }
  }
  float c = c0[j];   // replicated across lanes (identical updates keep it consistent)
  __syncthreads();   // smem tag zeroing complete (only barrier in the kernel)

  for (int s = 0; s < SEQ; ++s) {
    const unsigned need = (unsigned)s + 1u;        // tag of h^{(s)}
    const uint32_t par_off = (uint32_t)(s & 1) * (HID * 8);

    // prefetch this step's input-side gate values (long-scoreboard load,
    // overlaps the record polling below)
    float xgv = 0.0f;
    if (lane < 4) xgv = __ldg(g_xg + (size_t)s * G4 + j + (lane << 10));

    // --- fill: poll own 4 global records, then copy (with tags) into smem ---
    {
      const uint2* rp = &g_hrec[s & 1][tid << 2];
      uint4 a, b;
      do { a = ld_rec2(rp);     } while (a.y < need || a.w < need);
      do { b = ld_rec2(rp + 2); } while (b.y < need || b.w < need);
      const uint32_t daddr = par_off + (uint32_t)tid * 32;
      sts_rec2(sbase + daddr,      a);
      sts_rec2(sbase + daddr + 16, b);
    }

    // --- compute: consume chunks as their smem records become ready ---
    ull acc2[4];
    #pragma unroll
    for (int g = 0; g < 4; ++g) acc2[g] = 0ULL;
    #pragma unroll
    for (int i = 0; i < 16; ++i) {
      // records for columns 2*(lane+32i), 2*(lane+32i)+1
      const uint32_t caddr = par_off + (uint32_t)lane * 16 + (uint32_t)i * 512;
      uint4 r;
      do { r = lds_rec2(sbase + caddr); } while (r.y < need || r.w < need);
      ull hh = pk2(__uint_as_float(r.x), __uint_as_float(r.z));
      #pragma unroll
      for (int g = 0; g < 4; ++g) fma2(acc2[g], wreg[g][i], hh);
    }
    float acc[4];
    #pragma unroll
    for (int g = 0; g < 4; ++g) {
      float lo, hi; upk2(acc2[g], lo, hi);
      acc[g] = lo + hi;
    }
    // butterfly reduce: every lane ends with the full sums
    #pragma unroll
    for (int off = 16; off > 0; off >>= 1)
      #pragma unroll
      for (int g = 0; g < 4; ++g)
        acc[g] += __shfl_xor_sync(0xffffffffu, acc[g], off);

    float xg0 = __shfl_sync(0xffffffffu, xgv, 0);
    float xg1 = __shfl_sync(0xffffffffu, xgv, 1);
    float xg2 = __shfl_sync(0xffffffffu, xgv, 2);
    float xg3 = __shfl_sync(0xffffffffu, xgv, 3);

    // gate order i, f, g, o (PyTorch)
    float iv = sigm(acc[0] + xg0);
    float fv = sigm(acc[1] + xg1);
    float gv = tanh_(acc[2] + xg2);
    float ov = sigm(acc[3] + xg3);
    c = fv * c + iv * gv;
    float hn = ov * tanh_(c);

    // publish h^{(s+1)} immediately: slot (s+1)&1, tag s+2
    if (lane == 0)
      st_rec(&g_hrec[(s + 1) & 1][j], hn, (unsigned)s + 2u);
  }
}

// ==============================================================================
// Kernel 3: log_softmax over the final hidden state. h^{(4096)} sits in
// g_hrec[0][j].x (tag 4097). One CTA, 1024 threads.
// ==============================================================================
__global__ void lsm_kernel(float* __restrict__ out)
{
  const int tid  = threadIdx.x;
  const int lane = tid & 31;
  const int w    = tid >> 5;
  __shared__ float red[32];
  __shared__ float bcast[2];

  float v = __uint_as_float(g_hrec[0][tid].x);

  float m = v;
  #pragma unroll
  for (int o = 16; o > 0; o >>= 1) m = fmaxf(m, __shfl_xor_sync(0xffffffffu, m, o));
  if (lane == 0) red[w] = m;
  __syncthreads();
  if (tid < 32) {
    float x = red[tid];
    #pragma unroll
    for (int o = 16; o > 0; o >>= 1) x = fmaxf(x, __shfl_xor_sync(0xffffffffu, x, o));
    if (tid == 0) bcast[0] = x;
  }
  __syncthreads();
  m = bcast[0];

  float e = __expf(v - m);
  float s = e;
  #pragma unroll
  for (int o = 16; o > 0; o >>= 1) s += __shfl_xor_sync(0xffffffffu, s, o);
  if (lane == 0) red[w] = s;
  __syncthreads();
  if (tid < 32) {
    float x = red[tid];
    #pragma unroll
    for (int o = 16; o > 0; o >>= 1) x += __shfl_xor_sync(0xffffffffu, x, o);
    if (tid == 0) bcast[1] = logf(x);
  }
  __syncthreads();

  out[tid] = (v - m) - bcast[1];
}

// ==============================================================================
extern "C" void kernel_launch(void* const* d_in, const int* in_sizes, int n_in,
                              void* d_out, int out_size)
{
  const int*   inputs = (const int*)  d_in[0];
  const float* emb    = (const float*)d_in[1];
  const float* W_ih   = (const float*)d_in[2];
  const float* W_hh   = (const float*)d_in[3];
  const float* b_ih   = (const float*)d_in[4];
  const float* b_hh   = (const float*)d_in[5];
  const float* h0     = (const float*)d_in[6];
  const float* c0     = (const float*)d_in[7];
  float* out = (float*)d_out;

  dim3 grid(G4 / 128, SEQ / 128);
  xg_gemm<<<grid, 256>>>(inputs, emb, W_ih, b_ih, b_hh, h0);
  lstm_scan<<<NCTA, SCAN_THREADS>>>(W_hh, c0);
  lsm_kernel<<<1, HID>>>(out);
}

// round 11
// speedup vs baseline: 2.7186x; 2.7186x over previous
#include <cuda_runtime.h>
#include <cstdint>
#include <cstddef>

#define SEQ  4096
#define HID  1024
#define G4   4096
#define NCTA 128
#define SCAN_THREADS 256

typedef unsigned long long ull;

// ---------------- persistent device scratch (static: allocation-free) ----------
__device__ float g_xg[(size_t)SEQ * G4];   // 64 MB: precomputed input-side gates
// Tagged h records: (h value, tag) packed in 8B -> single-copy atomic.
// Record for h^{(s)} (state consumed at step s) lives in slot s&1 with tag s+1.
__device__ __align__(16) uint2 g_hrec[2][HID];   // 16 KB

// ---------------- packed f32x2 helpers ----------------------------------------
__device__ __forceinline__ ull pk2(float x, float y) {
  ull r; asm("mov.b64 %0, {%1, %2};" : "=l"(r) : "f"(x), "f"(y)); return r;
}
__device__ __forceinline__ void upk2(ull v, float& x, float& y) {
  asm("mov.b64 {%0, %1}, %2;" : "=f"(x), "=f"(y) : "l"(v));
}
__device__ __forceinline__ void fma2(ull& d, ull a, ull b) {
  asm("fma.rn.f32x2 %0, %1, %2, %0;" : "+l"(d) : "l"(a), "l"(b));
}

__device__ __forceinline__ float sigm(float x) {
  return __fdividef(1.0f, 1.0f + __expf(-x));
}
__device__ __forceinline__ float tanh_(float x) {
  float e = __expf(2.0f * x);
  return 1.0f - __fdividef(2.0f, e + 1.0f);
}

// strong (L2-coherent) 16B load: returns 2 records (h,tag,h,tag)
__device__ __forceinline__ uint4 ld_rec2(const uint2* p) {
  uint4 v;
  asm volatile("ld.relaxed.gpu.global.v4.b32 {%0,%1,%2,%3}, [%4];"
               : "=r"(v.x), "=r"(v.y), "=r"(v.z), "=r"(v.w) : "l"(p) : "memory");
  return v;
}
// strong 8B store: one record (h, tag) — tag travels with the payload
__device__ __forceinline__ void st_rec(uint2* p, float h, unsigned tag) {
  asm volatile("st.relaxed.gpu.global.v2.b32 [%0], {%1,%2};"
               :: "l"(p), "r"(__float_as_uint(h)), "r"(tag) : "memory");
}

// ==============================================================================
// Kernel 1: xg[m][n] = sum_k emb[inputs[m]][k] * W_ih[n][k] + b_ih[n] + b_hh[n]
// 128x128 tile, BK=8, 256 threads, 8x8 micro-tile via fma.rn.f32x2, 1-deep
// register prefetch pipeline. Block (0,0) also seeds the scan's h records:
// slot 0 = (h0, tag 1), slot 1 = zeros (stream-ordered before the scan).
// ==============================================================================
__global__ __launch_bounds__(256, 2) void xg_gemm(
    const int*   __restrict__ inputs,
    const float* __restrict__ emb,
    const float* __restrict__ Wih,
    const float* __restrict__ b_ih,
    const float* __restrict__ b_hh,
    const float* __restrict__ h0)
{
  if (blockIdx.x == 0 && blockIdx.y == 0) {
    for (int i = threadIdx.x; i < HID; i += 256) {
      g_hrec[0][i] = make_uint2(__float_as_uint(h0[i]), 1u);  // h^{(0)}, tag 1
      g_hrec[1][i] = make_uint2(0u, 0u);
    }
  }

  __shared__ __align__(16) float As[8][128];
  __shared__ __align__(16) float Bs[8][128];
  __shared__ int idx[128];

  const int tid = threadIdx.x;
  const int m0 = blockIdx.y << 7;
  const int n0 = blockIdx.x << 7;

  if (tid < 128) idx[tid] = inputs[m0 + tid];
  __syncthreads();

  const int lr = tid >> 1;           // 0..127 row for cooperative loads
  const int lk = (tid & 1) << 2;     // k offset 0 or 4
  const int tx = tid & 15;           // micro-tile col group
  const int ty = tid >> 4;           // micro-tile row group

  const float* aptr = emb + (size_t)idx[lr] * 1024 + lk;
  const float* bptr = Wih + (size_t)(n0 + lr) * 1024 + lk;

  ull acc2[8][4];
  #pragma unroll
  for (int i = 0; i < 8; ++i)
    #pragma unroll
    for (int p = 0; p < 4; ++p) acc2[i][p] = 0ULL;

  float4 av = *(const float4*)(aptr);
  float4 bv = *(const float4*)(bptr);

  for (int k0 = 0; k0 < 1024; k0 += 8) {
    __syncthreads();
    As[lk + 0][lr] = av.x; As[lk + 1][lr] = av.y;
    As[lk + 2][lr] = av.z; As[lk + 3][lr] = av.w;
    Bs[lk + 0][lr] = bv.x; Bs[lk + 1][lr] = bv.y;
    Bs[lk + 2][lr] = bv.z; Bs[lk + 3][lr] = bv.w;
    __syncthreads();

    const int kn = (k0 + 8 < 1024) ? (k0 + 8) : 0;
    av = *(const float4*)(aptr + kn);
    bv = *(const float4*)(bptr + kn);

    #pragma unroll
    for (int kk = 0; kk < 8; ++kk) {
      float4 a0 = *(const float4*)&As[kk][ty << 3];
      float4 a1 = *(const float4*)&As[kk][(ty << 3) + 4];
      float4 b0 = *(const float4*)&Bs[kk][tx << 3];
      float4 b1 = *(const float4*)&Bs[kk][(tx << 3) + 4];
      ull bq[4];
      bq[0] = pk2(b0.x, b0.y); bq[1] = pk2(b0.z, b0.w);
      bq[2] = pk2(b1.x, b1.y); bq[3] = pk2(b1.z, b1.w);
      float a[8] = {a0.x, a0.y, a0.z, a0.w, a1.x, a1.y, a1.z, a1.w};
      #pragma unroll
      for (int i = 0; i < 8; ++i) {
        ull ad = pk2(a[i], a[i]);
        #pragma unroll
        for (int p = 0; p < 4; ++p) fma2(acc2[i][p], ad, bq[p]);
      }
    }
  }

  float bias[8];
  #pragma unroll
  for (int p = 0; p < 8; ++p) {
    int n = n0 + (tx << 3) + p;
    bias[p] = b_ih[n] + b_hh[n];
  }
  #pragma unroll
  for (int i = 0; i < 8; ++i) {
    float c[8];
    #pragma unroll
    for (int p = 0; p < 4; ++p) upk2(acc2[i][p], c[2 * p], c[2 * p + 1]);
    #pragma unroll
    for (int p = 0; p < 8; ++p) c[p] += bias[p];
    int m = m0 + (ty << 3) + i;
    float* outp = g_xg + (size_t)m * G4 + n0 + (tx << 3);
    *(float4*)(outp)     = make_float4(c[0], c[1], c[2], c[3]);
    *(float4*)(outp + 4) = make_float4(c[4], c[5], c[6], c[7]);
  }
}

// ==============================================================================
// Kernel 2: persistent LSTM scan (round-7 protocol + three refinements).
// 128 CTAs x 256 threads. CTA b owns h columns [8b, 8b+8), warp w -> column j.
//
// Per step: (1) each thread polls its OWN 4 global records with BOTH 16B loads
// in flight per iteration (MLP=2); tag+payload arrive in the same load, so one
// L2 round trip gives sync AND data. (2) payloads only (tags stripped) go into
// parity-doubled sh_h via one STS.128. (3) single __syncthreads, then the FMA
// block reads LDS.64 chunks; publish per-warp the moment gates finish — no
// trailing barrier (parity smem + the one barrier make the WAR safe: a fill
// into slot s&1 at step s+2 is separated from step-s reads by barrier(s+1)).
// ==============================================================================
__global__ __launch_bounds__(SCAN_THREADS, 1) void lstm_scan(
    const float* __restrict__ W_hh,
    const float* __restrict__ c0)
{
  const int tid  = threadIdx.x;
  const int lane = tid & 31;
  const int w    = tid >> 5;                  // warp 0..7
  const int j    = (blockIdx.x << 3) + w;     // 0..1023

  __shared__ __align__(16) float sh_h[2][HID];   // parity-doubled, 8 KB

  // load this thread's 128 weights (as 64 f32x2 pairs) into registers
  ull wreg[4][16];
  #pragma unroll
  for (int g = 0; g < 4; ++g) {
    const float* wp = W_hh + (size_t)(j + (g << 10)) * HID;
    #pragma unroll
    for (int i = 0; i < 16; ++i) {
      float2 v = *(const float2*)(wp + 2 * (lane + 32 * i));
      wreg[g][i] = pk2(v.x, v.y);
    }
  }
  float c = c0[j];   // replicated across lanes (identical updates keep it consistent)

  for (int s = 0; s < SEQ; ++s) {
    const unsigned need = (unsigned)s + 1u;        // tag of h^{(s)}
    const int par = s & 1;

    // prefetch this step's input-side gate values (long-scoreboard load,
    // overlaps the record polling below)
    float xgv = 0.0f;
    if (lane < 4) xgv = __ldg(g_xg + (size_t)s * G4 + j + (lane << 10));

    // --- fill: poll own 4 global records (both loads in flight), stage to smem
    {
      const uint2* rp = &g_hrec[par][tid << 2];
      uint4 a, b;
      do {
        a = ld_rec2(rp);
        b = ld_rec2(rp + 2);
      } while (a.y < need || a.w < need || b.y < need || b.w < need);
      ((float4*)sh_h[par])[tid] =
          make_float4(__uint_as_float(a.x), __uint_as_float(a.z),
                      __uint_as_float(b.x), __uint_as_float(b.z));
    }
    __syncthreads();   // the only barrier in the step

    // --- 4 dot products of length 1024, f32x2 packed, LDS.64 per chunk ---
    ull acc2[4];
    #pragma unroll
    for (int g = 0; g < 4; ++g) acc2[g] = 0ULL;
    #pragma unroll
    for (int i = 0; i < 16; ++i) {
      ull hh = *(const ull*)(sh_h[par] + 2 * (lane + 32 * i));
      #pragma unroll
      for (int g = 0; g < 4; ++g) fma2(acc2[g], wreg[g][i], hh);
    }
    float acc[4];
    #pragma unroll
    for (int g = 0; g < 4; ++g) {
      float lo, hi; upk2(acc2[g], lo, hi);
      acc[g] = lo + hi;
    }
    // butterfly reduce: every lane ends with the full sums
    #pragma unroll
    for (int off = 16; off > 0; off >>= 1)
      #pragma unroll
      for (int g = 0; g < 4; ++g)
        acc[g] += __shfl_xor_sync(0xffffffffu, acc[g], off);

    float xg0 = __shfl_sync(0xffffffffu, xgv, 0);
    float xg1 = __shfl_sync(0xffffffffu, xgv, 1);
    float xg2 = __shfl_sync(0xffffffffu, xgv, 2);
    float xg3 = __shfl_sync(0xffffffffu, xgv, 3);

    // gate order i, f, g, o (PyTorch)
    float iv = sigm(acc[0] + xg0);
    float fv = sigm(acc[1] + xg1);
    float gv = tanh_(acc[2] + xg2);
    float ov = sigm(acc[3] + xg3);
    c = fv * c + iv * gv;
    float hn = ov * tanh_(c);

    // publish h^{(s+1)} immediately: slot (s+1)&1, tag s+2 — no trailing barrier
    if (lane == 0)
      st_rec(&g_hrec[(s + 1) & 1][j], hn, (unsigned)s + 2u);
  }
}

// ==============================================================================
// Kernel 3: log_softmax over the final hidden state. h^{(4096)} sits in
// g_hrec[0][j].x (tag 4097). One CTA, 1024 threads.
// ==============================================================================
__global__ void lsm_kernel(float* __restrict__ out)
{
  const int tid  = threadIdx.x;
  const int lane = tid & 31;
  const int w    = tid >> 5;
  __shared__ float red[32];
  __shared__ float bcast[2];

  float v = __uint_as_float(g_hrec[0][tid].x);

  float m = v;
  #pragma unroll
  for (int o = 16; o > 0; o >>= 1) m = fmaxf(m, __shfl_xor_sync(0xffffffffu, m, o));
  if (lane == 0) red[w] = m;
  __syncthreads();
  if (tid < 32) {
    float x = red[tid];
    #pragma unroll
    for (int o = 16; o > 0; o >>= 1) x = fmaxf(x, __shfl_xor_sync(0xffffffffu, x, o));
    if (tid == 0) bcast[0] = x;
  }
  __syncthreads();
  m = bcast[0];

  float e = __expf(v - m);
  float s = e;
  #pragma unroll
  for (int o = 16; o > 0; o >>= 1) s += __shfl_xor_sync(0xffffffffu, s, o);
  if (lane == 0) red[w] = s;
  __syncthreads();
  if (tid < 32) {
    float x = red[tid];
    #pragma unroll
    for (int o = 16; o > 0; o >>= 1) x += __shfl_xor_sync(0xffffffffu, x, o);
    if (tid == 0) bcast[1] = logf(x);
  }
  __syncthreads();

  out[tid] = (v - m) - bcast[1];
}

// ==============================================================================
extern "C" void kernel_launch(void* const* d_in, const int* in_sizes, int n_in,
                              void* d_out, int out_size)
{
  const int*   inputs = (const int*)  d_in[0];
  const float* emb    = (const float*)d_in[1];
  const float* W_ih   = (const float*)d_in[2];
  const float* W_hh   = (const float*)d_in[3];
  const float* b_ih   = (const float*)d_in[4];
  const float* b_hh   = (const float*)d_in[5];
  const float* h0     = (const float*)d_in[6];
  const float* c0     = (const float*)d_in[7];
  float* out = (float*)d_out;

  dim3 grid(G4 / 128, SEQ / 128);
  xg_gemm<<<grid, 256>>>(inputs, emb, W_ih, b_ih, b_hh, h0);
  lstm_scan<<<NCTA, SCAN_THREADS>>>(W_hh, c0);
  lsm_kernel<<<1, HID>>>(out);
}

// round 13
// speedup vs baseline: 3.3138x; 1.2189x over previous
#include <cuda_runtime.h>
#include <cstdint>
#include <cstddef>

#define SEQ  4096
#define HID  1024
#define G4   4096
#define NCTA 128
#define SCAN_THREADS 256

typedef unsigned long long ull;

// ---------------- persistent device scratch (static: allocation-free) ----------
__device__ float g_xg[(size_t)SEQ * G4];   // 64 MB: precomputed input-side gates
// Tagged h records: (h value, tag) packed in 8B -> single-copy atomic.
// Record for h^{(s)} (state consumed at step s) lives in slot s&1 with tag s+1.
__device__ __align__(16) uint2 g_hrec[2][HID];   // 16 KB

// ---------------- packed f32x2 helpers ----------------------------------------
__device__ __forceinline__ ull pk2(float x, float y) {
  ull r; asm("mov.b64 %0, {%1, %2};" : "=l"(r) : "f"(x), "f"(y)); return r;
}
__device__ __forceinline__ void upk2(ull v, float& x, float& y) {
  asm("mov.b64 {%0, %1}, %2;" : "=f"(x), "=f"(y) : "l"(v));
}
__device__ __forceinline__ void fma2(ull& d, ull a, ull b) {
  asm("fma.rn.f32x2 %0, %1, %2, %0;" : "+l"(d) : "l"(a), "l"(b));
}

__device__ __forceinline__ float sigm(float x) {
  return __fdividef(1.0f, 1.0f + __expf(-x));
}
__device__ __forceinline__ float tanh_(float x) {
  float e = __expf(2.0f * x);
  return 1.0f - __fdividef(2.0f, e + 1.0f);
}

// strong (L2-coherent) 16B load: returns 2 records (h,tag,h,tag)
__device__ __forceinline__ uint4 ld_rec2(const uint2* p) {
  uint4 v;
  asm volatile("ld.relaxed.gpu.global.v4.b32 {%0,%1,%2,%3}, [%4];"
               : "=r"(v.x), "=r"(v.y), "=r"(v.z), "=r"(v.w) : "l"(p) : "memory");
  return v;
}
// strong 8B store: one record (h, tag) — tag travels with the payload
__device__ __forceinline__ void st_rec(uint2* p, float h, unsigned tag) {
  asm volatile("st.relaxed.gpu.global.v2.b32 [%0], {%1,%2};"
               :: "l"(p), "r"(__float_as_uint(h)), "r"(tag) : "memory");
}

// ==============================================================================
// Kernel 1: xg[m][n] = sum_k emb[inputs[m]][k] * W_ih[n][k] + b_ih[n] + b_hh[n]
// 128x128 tile, BK=8, 256 threads, 8x8 micro-tile via fma.rn.f32x2, 1-deep
// register prefetch pipeline. Block (0,0) also seeds the scan's h records:
// slot 0 = (h0, tag 1), slot 1 = zeros (stream-ordered before the scan).
// ==============================================================================
__global__ __launch_bounds__(256, 2) void xg_gemm(
    const int*   __restrict__ inputs,
    const float* __restrict__ emb,
    const float* __restrict__ Wih,
    const float* __restrict__ b_ih,
    const float* __restrict__ b_hh,
    const float* __restrict__ h0)
{
  if (blockIdx.x == 0 && blockIdx.y == 0) {
    for (int i = threadIdx.x; i < HID; i += 256) {
      g_hrec[0][i] = make_uint2(__float_as_uint(h0[i]), 1u);  // h^{(0)}, tag 1
      g_hrec[1][i] = make_uint2(0u, 0u);
    }
  }

  __shared__ __align__(16) float As[8][128];
  __shared__ __align__(16) float Bs[8][128];
  __shared__ int idx[128];

  const int tid = threadIdx.x;
  const int m0 = blockIdx.y << 7;
  const int n0 = blockIdx.x << 7;

  if (tid < 128) idx[tid] = inputs[m0 + tid];
  __syncthreads();

  const int lr = tid >> 1;           // 0..127 row for cooperative loads
  const int lk = (tid & 1) << 2;     // k offset 0 or 4
  const int tx = tid & 15;           // micro-tile col group
  const int ty = tid >> 4;           // micro-tile row group

  const float* aptr = emb + (size_t)idx[lr] * 1024 + lk;
  const float* bptr = Wih + (size_t)(n0 + lr) * 1024 + lk;

  ull acc2[8][4];
  #pragma unroll
  for (int i = 0; i < 8; ++i)
    #pragma unroll
    for (int p = 0; p < 4; ++p) acc2[i][p] = 0ULL;

  float4 av = *(const float4*)(aptr);
  float4 bv = *(const float4*)(bptr);

  for (int k0 = 0; k0 < 1024; k0 += 8) {
    __syncthreads();
    As[lk + 0][lr] = av.x; As[lk + 1][lr] = av.y;
    As[lk + 2][lr] = av.z; As[lk + 3][lr] = av.w;
    Bs[lk + 0][lr] = bv.x; Bs[lk + 1][lr] = bv.y;
    Bs[lk + 2][lr] = bv.z; Bs[lk + 3][lr] = bv.w;
    __syncthreads();

    const int kn = (k0 + 8 < 1024) ? (k0 + 8) : 0;
    av = *(const float4*)(aptr + kn);
    bv = *(const float4*)(bptr + kn);

    #pragma unroll
    for (int kk = 0; kk < 8; ++kk) {
      float4 a0 = *(const float4*)&As[kk][ty << 3];
      float4 a1 = *(const float4*)&As[kk][(ty << 3) + 4];
      float4 b0 = *(const float4*)&Bs[kk][tx << 3];
      float4 b1 = *(const float4*)&Bs[kk][(tx << 3) + 4];
      ull bq[4];
      bq[0] = pk2(b0.x, b0.y); bq[1] = pk2(b0.z, b0.w);
      bq[2] = pk2(b1.x, b1.y); bq[3] = pk2(b1.z, b1.w);
      float a[8] = {a0.x, a0.y, a0.z, a0.w, a1.x, a1.y, a1.z, a1.w};
      #pragma unroll
      for (int i = 0; i < 8; ++i) {
        ull ad = pk2(a[i], a[i]);
        #pragma unroll
        for (int p = 0; p < 4; ++p) fma2(acc2[i][p], ad, bq[p]);
      }
    }
  }

  float bias[8];
  #pragma unroll
  for (int p = 0; p < 8; ++p) {
    int n = n0 + (tx << 3) + p;
    bias[p] = b_ih[n] + b_hh[n];
  }
  #pragma unroll
  for (int i = 0; i < 8; ++i) {
    float c[8];
    #pragma unroll
    for (int p = 0; p < 4; ++p) upk2(acc2[i][p], c[2 * p], c[2 * p + 1]);
    #pragma unroll
    for (int p = 0; p < 8; ++p) c[p] += bias[p];
    int m = m0 + (ty << 3) + i;
    float* outp = g_xg + (size_t)m * G4 + n0 + (tx << 3);
    *(float4*)(outp)     = make_float4(c[0], c[1], c[2], c[3]);
    *(float4*)(outp + 4) = make_float4(c[4], c[5], c[6], c[7]);
  }
}

// ==============================================================================
// Kernel 2: persistent LSTM scan. 128 CTAs x 256 threads; CTA b owns h columns
// [8b, 8b+8), warp w -> column j. Round-7 protocol with two refinements kept
// from round 11 (merged MLP=2 poll loop; payload-only smem staging) and the
// trailing __syncthreads RESTORED — it throttles poll traffic so spin loops
// only run in the post-barrier window (round 11 showed unthrottled polling
// costs ~4 ms). Parity-doubled sh_h retained (harmless with both barriers).
// ==============================================================================
__global__ __launch_bounds__(SCAN_THREADS, 1) void lstm_scan(
    const float* __restrict__ W_hh,
    const float* __restrict__ c0)
{
  const int tid  = threadIdx.x;
  const int lane = tid & 31;
  const int w    = tid >> 5;                  // warp 0..7
  const int j    = (blockIdx.x << 3) + w;     // 0..1023

  __shared__ __align__(16) float sh_h[2][HID];   // parity-doubled, 8 KB

  // load this thread's 128 weights (as 64 f32x2 pairs) into registers
  ull wreg[4][16];
  #pragma unroll
  for (int g = 0; g < 4; ++g) {
    const float* wp = W_hh + (size_t)(j + (g << 10)) * HID;
    #pragma unroll
    for (int i = 0; i < 16; ++i) {
      float2 v = *(const float2*)(wp + 2 * (lane + 32 * i));
      wreg[g][i] = pk2(v.x, v.y);
    }
  }
  float c = c0[j];   // replicated across lanes (identical updates keep it consistent)

  for (int s = 0; s < SEQ; ++s) {
    const unsigned need = (unsigned)s + 1u;        // tag of h^{(s)}
    const int par = s & 1;

    // prefetch this step's input-side gate values (long-scoreboard load,
    // overlaps the record polling below)
    float xgv = 0.0f;
    if (lane < 4) xgv = __ldg(g_xg + (size_t)s * G4 + j + (lane << 10));

    // --- fill: poll own 4 global records (both 16B loads in flight, MLP=2) ---
    {
      const uint2* rp = &g_hrec[par][tid << 2];
      uint4 a, b;
      do {
        a = ld_rec2(rp);
        b = ld_rec2(rp + 2);
      } while (a.y < need || a.w < need || b.y < need || b.w < need);
      // payloads only into smem (tags stripped) — one STS.128
      ((float4*)sh_h[par])[tid] =
          make_float4(__uint_as_float(a.x), __uint_as_float(a.z),
                      __uint_as_float(b.x), __uint_as_float(b.z));
    }
    __syncthreads();

    // --- 4 dot products of length 1024, f32x2 packed, LDS.64 per chunk ---
    ull acc2[4];
    #pragma unroll
    for (int g = 0; g < 4; ++g) acc2[g] = 0ULL;
    #pragma unroll
    for (int i = 0; i < 16; ++i) {
      ull hh = *(const ull*)(sh_h[par] + 2 * (lane + 32 * i));
      #pragma unroll
      for (int g = 0; g < 4; ++g) fma2(acc2[g], wreg[g][i], hh);
    }
    float acc[4];
    #pragma unroll
    for (int g = 0; g < 4; ++g) {
      float lo, hi; upk2(acc2[g], lo, hi);
      acc[g] = lo + hi;
    }
    // butterfly reduce: every lane ends with the full sums
    #pragma unroll
    for (int off = 16; off > 0; off >>= 1)
      #pragma unroll
      for (int g = 0; g < 4; ++g)
        acc[g] += __shfl_xor_sync(0xffffffffu, acc[g], off);

    float xg0 = __shfl_sync(0xffffffffu, xgv, 0);
    float xg1 = __shfl_sync(0xffffffffu, xgv, 1);
    float xg2 = __shfl_sync(0xffffffffu, xgv, 2);
    float xg3 = __shfl_sync(0xffffffffu, xgv, 3);

    // gate order i, f, g, o (PyTorch)
    float iv = sigm(acc[0] + xg0);
    float fv = sigm(acc[1] + xg1);
    float gv = tanh_(acc[2] + xg2);
    float ov = sigm(acc[3] + xg3);
    c = fv * c + iv * gv;
    float hn = ov * tanh_(c);

    // publish h^{(s+1)}: slot (s+1)&1, tag s+2
    if (lane == 0)
      st_rec(&g_hrec[(s + 1) & 1][j], hn, (unsigned)s + 2u);

    // throttle: no warp may advance to next step's poll loop until all warps
    // in this CTA have finished (keeps spin traffic off the LSU while
    // siblings compute; empirically worth ~4 ms — see round 11)
    __syncthreads();
  }
}

// ==============================================================================
// Kernel 3: log_softmax over the final hidden state. h^{(4096)} sits in
// g_hrec[0][j].x (tag 4097). One CTA, 1024 threads.
// ==============================================================================
__global__ void lsm_kernel(float* __restrict__ out)
{
  const int tid  = threadIdx.x;
  const int lane = tid & 31;
  const int w    = tid >> 5;
  __shared__ float red[32];
  __shared__ float bcast[2];

  float v = __uint_as_float(g_hrec[0][tid].x);

  float m = v;
  #pragma unroll
  for (int o = 16; o > 0; o >>= 1) m = fmaxf(m, __shfl_xor_sync(0xffffffffu, m, o));
  if (lane == 0) red[w] = m;
  __syncthreads();
  if (tid < 32) {
    float x = red[tid];
    #pragma unroll
    for (int o = 16; o > 0; o >>= 1) x = fmaxf(x, __shfl_xor_sync(0xffffffffu, x, o));
    if (tid == 0) bcast[0] = x;
  }
  __syncthreads();
  m = bcast[0];

  float e = __expf(v - m);
  float s = e;
  #pragma unroll
  for (int o = 16; o > 0; o >>= 1) s += __shfl_xor_sync(0xffffffffu, s, o);
  if (lane == 0) red[w] = s;
  __syncthreads();
  if (tid < 32) {
    float x = red[tid];
    #pragma unroll
    for (int o = 16; o > 0; o >>= 1) x += __shfl_xor_sync(0xffffffffu, x, o);
    if (tid == 0) bcast[1] = logf(x);
  }
  __syncthreads();

  out[tid] = (v - m) - bcast[1];
}

// ==============================================================================
extern "C" void kernel_launch(void* const* d_in, const int* in_sizes, int n_in,
                              void* d_out, int out_size)
{
  const int*   inputs = (const int*)  d_in[0];
  const float* emb    = (const float*)d_in[1];
  const float* W_ih   = (const float*)d_in[2];
  const float* W_hh   = (const float*)d_in[3];
  const float* b_ih   = (const float*)d_in[4];
  const float* b_hh   = (const float*)d_in[5];
  const float* h0     = (const float*)d_in[6];
  const float* c0     = (const float*)d_in[7];
  float* out = (float*)d_out;

  dim3 grid(G4 / 128, SEQ / 128);
  xg_gemm<<<grid, 256>>>(inputs, emb, W_ih, b_ih, b_hh, h0);
  lstm_scan<<<NCTA, SCAN_THREADS>>>(W_hh, c0);
  lsm_kernel<<<1, HID>>>(out);
}